// round 8
// baseline (speedup 1.0000x reference)
#include <cuda_runtime.h>
#include <cuda_bf16.h>

// ---------------- problem constants ----------------
#define DD 256
#define HH 8
#define N_MAX 50048
#define E_MAX 800000
#define NEG_SLOPE 0.2f

// ---------------- device scratch ----------------
__device__ __align__(256) float g_xp  [N_MAX * DD];
__device__ __align__(256) float g_asrc[N_MAX * HH];
__device__ __align__(256) float g_adst[N_MAX * HH];
__device__ __align__(256) float g_hn  [N_MAX * DD];
__device__ __align__(256) float g_hid [N_MAX * DD];
__device__ __align__(256) int   g_deg [N_MAX];
__device__ __align__(256) int   g_off [N_MAX];
__device__ __align__(256) int   g_cur [N_MAX];
__device__ __align__(256) int   g_srcl[E_MAX];
__device__ int g_bsum[64];

__device__ __forceinline__ float leaky(float v) {
    return v > 0.f ? v : NEG_SLOPE * v;
}

// ---------------- bf16-split helpers ----------------
// low half = hi16(x), high half = hi16(y)  (x is the first K value)
__device__ __forceinline__ unsigned pack_hi(float x, float y) {
    unsigned r;
    asm("prmt.b32 %0, %1, %2, 0x7632;"
        : "=r"(r) : "r"(__float_as_uint(x)), "r"(__float_as_uint(y)));
    return r;
}
__device__ __forceinline__ unsigned pack_lo(float x, float y) {
    float hx = __uint_as_float(__float_as_uint(x) & 0xffff0000u);
    float hy = __uint_as_float(__float_as_uint(y) & 0xffff0000u);
    float lx = x - hx, ly = y - hy;
    unsigned r;
    asm("cvt.rn.bf16x2.f32 %0, %1, %2;" : "=r"(r) : "f"(ly), "f"(lx));
    return r;
}

__device__ __forceinline__ void mma16(float* c, const unsigned* a, const unsigned* b) {
    asm("mma.sync.aligned.m16n8k16.row.col.f32.bf16.bf16.f32 "
        "{%0,%1,%2,%3}, {%4,%5,%6,%7}, {%8,%9}, {%0,%1,%2,%3};"
        : "+f"(c[0]), "+f"(c[1]), "+f"(c[2]), "+f"(c[3])
        : "r"(a[0]), "r"(a[1]), "r"(a[2]), "r"(a[3]), "r"(b[0]), "r"(b[1]));
}

// ---------------- tensor-core GEMM (3xBF16 split, pre-split smem planes) ----------------
// block: 256 threads = 8 warps (4m x 2n), tile 128 x 64; warp tile 32 x 32
// smem holds bf16x2 K-pair words: hi and lo planes, packed once at tile store.
template <bool RELU, bool BIAS>
__global__ __launch_bounds__(256)
void gemm_tc(const float* __restrict__ A, const float* __restrict__ B,
             const float* __restrict__ bias, float* __restrict__ C, int M) {
    __shared__ unsigned Ah[128][20], Al[128][20];   // [row][kpair], pad 20
    __shared__ unsigned Bh[16][68],  Bl[16][68];    // [kpair][col], pad 68
    const int tid  = threadIdx.x;
    const int lane = tid & 31;
    const int warp = tid >> 5;
    const int wm   = warp & 3;
    const int wn   = warp >> 2;
    const int brow = blockIdx.x * 128;
    const int bcol = blockIdx.y * 64;
    const int q    = lane >> 2;
    const int tq   = lane & 3;

    const int ar0 = tid >> 3;            // A row (4 rows per thread, +32 apart)
    const int ac4 = (tid & 7) * 4;       // A K offset (float4)
    const int ap0 = ac4 >> 1;            // A kpair base
    const int bp  = tid >> 4;            // B kpair (0..15)
    const int bc4 = (tid & 15) * 4;      // B col offset

    float acc[2][4][4];
#pragma unroll
    for (int mt = 0; mt < 2; mt++)
#pragma unroll
        for (int nt = 0; nt < 4; nt++)
#pragma unroll
            for (int k = 0; k < 4; k++) acc[mt][nt][k] = 0.f;

    float4 pa[4], pbu, pbw;

    // prologue: global load tile 0
#pragma unroll
    for (int j = 0; j < 4; j++) {
        int gr = brow + ar0 + 32 * j;
        pa[j] = (gr < M) ? *(const float4*)(A + gr * 256 + ac4)
                         : make_float4(0.f, 0.f, 0.f, 0.f);
    }
    pbu = *(const float4*)(B + (2 * bp)     * 256 + bcol + bc4);
    pbw = *(const float4*)(B + (2 * bp + 1) * 256 + bcol + bc4);

    // split + store tile 0
#pragma unroll
    for (int j = 0; j < 4; j++) {
        int r = ar0 + 32 * j;
        Ah[r][ap0]     = pack_hi(pa[j].x, pa[j].y);
        Ah[r][ap0 + 1] = pack_hi(pa[j].z, pa[j].w);
        Al[r][ap0]     = pack_lo(pa[j].x, pa[j].y);
        Al[r][ap0 + 1] = pack_lo(pa[j].z, pa[j].w);
    }
    Bh[bp][bc4]     = pack_hi(pbu.x, pbw.x);
    Bh[bp][bc4 + 1] = pack_hi(pbu.y, pbw.y);
    Bh[bp][bc4 + 2] = pack_hi(pbu.z, pbw.z);
    Bh[bp][bc4 + 3] = pack_hi(pbu.w, pbw.w);
    Bl[bp][bc4]     = pack_lo(pbu.x, pbw.x);
    Bl[bp][bc4 + 1] = pack_lo(pbu.y, pbw.y);
    Bl[bp][bc4 + 2] = pack_lo(pbu.z, pbw.z);
    Bl[bp][bc4 + 3] = pack_lo(pbu.w, pbw.w);
    __syncthreads();

    for (int k0 = 0; k0 < 8; k0++) {
        // prefetch next tile into registers
        if (k0 < 7) {
            int kb = (k0 + 1) * 32;
#pragma unroll
            for (int j = 0; j < 4; j++) {
                int gr = brow + ar0 + 32 * j;
                pa[j] = (gr < M) ? *(const float4*)(A + gr * 256 + kb + ac4)
                                 : make_float4(0.f, 0.f, 0.f, 0.f);
            }
            pbu = *(const float4*)(B + (kb + 2 * bp)     * 256 + bcol + bc4);
            pbw = *(const float4*)(B + (kb + 2 * bp + 1) * 256 + bcol + bc4);
        }

        // compute: pure LDS + MMA
#pragma unroll
        for (int kk = 0; kk < 2; kk++) {
            const int kb2 = kk * 8;      // kpair base
            unsigned bh[4][2], bl[4][2];
#pragma unroll
            for (int nt = 0; nt < 4; nt++) {
                int col = wn * 32 + nt * 8 + q;
                bh[nt][0] = Bh[kb2 + tq][col];
                bh[nt][1] = Bh[kb2 + 4 + tq][col];
                bl[nt][0] = Bl[kb2 + tq][col];
                bl[nt][1] = Bl[kb2 + 4 + tq][col];
            }
            unsigned ah[2][4], al[2][4];
#pragma unroll
            for (int mt = 0; mt < 2; mt++) {
                int r0 = wm * 32 + mt * 16 + q;
                ah[mt][0] = Ah[r0][kb2 + tq];
                ah[mt][1] = Ah[r0 + 8][kb2 + tq];
                ah[mt][2] = Ah[r0][kb2 + 4 + tq];
                ah[mt][3] = Ah[r0 + 8][kb2 + 4 + tq];
                al[mt][0] = Al[r0][kb2 + tq];
                al[mt][1] = Al[r0 + 8][kb2 + tq];
                al[mt][2] = Al[r0][kb2 + 4 + tq];
                al[mt][3] = Al[r0 + 8][kb2 + 4 + tq];
            }
#pragma unroll
            for (int mt = 0; mt < 2; mt++)
#pragma unroll
                for (int nt = 0; nt < 4; nt++) {
                    mma16(acc[mt][nt], al[mt], bh[nt]);
                    mma16(acc[mt][nt], ah[mt], bl[nt]);
                    mma16(acc[mt][nt], ah[mt], bh[nt]);
                }
        }
        __syncthreads();
        if (k0 < 7) {
#pragma unroll
            for (int j = 0; j < 4; j++) {
                int r = ar0 + 32 * j;
                Ah[r][ap0]     = pack_hi(pa[j].x, pa[j].y);
                Ah[r][ap0 + 1] = pack_hi(pa[j].z, pa[j].w);
                Al[r][ap0]     = pack_lo(pa[j].x, pa[j].y);
                Al[r][ap0 + 1] = pack_lo(pa[j].z, pa[j].w);
            }
            Bh[bp][bc4]     = pack_hi(pbu.x, pbw.x);
            Bh[bp][bc4 + 1] = pack_hi(pbu.y, pbw.y);
            Bh[bp][bc4 + 2] = pack_hi(pbu.z, pbw.z);
            Bh[bp][bc4 + 3] = pack_hi(pbu.w, pbw.w);
            Bl[bp][bc4]     = pack_lo(pbu.x, pbw.x);
            Bl[bp][bc4 + 1] = pack_lo(pbu.y, pbw.y);
            Bl[bp][bc4 + 2] = pack_lo(pbu.z, pbw.z);
            Bl[bp][bc4 + 3] = pack_lo(pbu.w, pbw.w);
            __syncthreads();
        }
    }

    // epilogue
#pragma unroll
    for (int mt = 0; mt < 2; mt++) {
        int gr0 = brow + wm * 32 + mt * 16 + q;
#pragma unroll
        for (int nt = 0; nt < 4; nt++) {
            int gc = bcol + wn * 32 + nt * 8 + 2 * tq;
            float bx = 0.f, by = 0.f;
            if (BIAS) { bx = bias[gc]; by = bias[gc + 1]; }
            float2 v0 = make_float2(acc[mt][nt][0] + bx, acc[mt][nt][1] + by);
            float2 v1 = make_float2(acc[mt][nt][2] + bx, acc[mt][nt][3] + by);
            if (RELU) {
                v0.x = fmaxf(v0.x, 0.f); v0.y = fmaxf(v0.y, 0.f);
                v1.x = fmaxf(v1.x, 0.f); v1.y = fmaxf(v1.y, 0.f);
            }
            if (gr0 < M)     *(float2*)(C + gr0 * 256 + gc)       = v0;
            if (gr0 + 8 < M) *(float2*)(C + (gr0 + 8) * 256 + gc) = v1;
        }
    }
}

// ---------------- per-node attention logits (warp per node) ----------------
__global__ void node_att(const float* __restrict__ att_src,
                         const float* __restrict__ att_dst, int n) {
    int warp = (blockIdx.x * blockDim.x + threadIdx.x) >> 5;
    int lane = threadIdx.x & 31;
    if (warp >= n) return;
    const int i = warp;
    const float4* xp = (const float4*)(g_xp + i * 256);
    float4 v0 = xp[lane * 2];
    float4 v1 = xp[lane * 2 + 1];
    const float4* as4 = (const float4*)att_src;
    const float4* ad4 = (const float4*)att_dst;
    float4 s0 = as4[lane * 2], s1 = as4[lane * 2 + 1];
    float4 d0 = ad4[lane * 2], d1 = ad4[lane * 2 + 1];
    float s = v0.x * s0.x + v0.y * s0.y + v0.z * s0.z + v0.w * s0.w
            + v1.x * s1.x + v1.y * s1.y + v1.z * s1.z + v1.w * s1.w;
    float d = v0.x * d0.x + v0.y * d0.y + v0.z * d0.z + v0.w * d0.w
            + v1.x * d1.x + v1.y * d1.y + v1.z * d1.z + v1.w * d1.w;
    s += __shfl_xor_sync(0xffffffffu, s, 1);
    s += __shfl_xor_sync(0xffffffffu, s, 2);
    d += __shfl_xor_sync(0xffffffffu, d, 1);
    d += __shfl_xor_sync(0xffffffffu, d, 2);
    if ((lane & 3) == 0) {
        int h = lane >> 2;
        g_asrc[i * 8 + h] = s;
        g_adst[i * 8 + h] = d;
    }
}

// ---------------- CSR build ----------------
__global__ void deg_count(const int* __restrict__ ei, int E) {
    int e = blockIdx.x * blockDim.x + threadIdx.x;
    if (e >= E) return;
    atomicAdd(&g_deg[ei[E + e]], 1);
}

__global__ void scan_part(int n) {
    __shared__ int wsum[32];
    int tid = threadIdx.x, lane = tid & 31, wid = tid >> 5;
    int n4 = (n + 3) >> 2;
    int f = blockIdx.x * 1024 + tid;
    int4 v = make_int4(0, 0, 0, 0);
    if (f < n4) {
        if (f * 4 + 3 < n) v = ((const int4*)g_deg)[f];
        else {
            if (f * 4 + 0 < n) v.x = g_deg[f * 4 + 0];
            if (f * 4 + 1 < n) v.y = g_deg[f * 4 + 1];
            if (f * 4 + 2 < n) v.z = g_deg[f * 4 + 2];
        }
    }
    int tsum = v.x + v.y + v.z + v.w;
    int x = tsum;
#pragma unroll
    for (int o = 1; o < 32; o <<= 1) {
        int t = __shfl_up_sync(0xffffffffu, x, o);
        if (lane >= o) x += t;
    }
    if (lane == 31) wsum[wid] = x;
    __syncthreads();
    if (wid == 0) {
        int w = wsum[lane];
#pragma unroll
        for (int o = 1; o < 32; o <<= 1) {
            int t = __shfl_up_sync(0xffffffffu, w, o);
            if (lane >= o) w += t;
        }
        wsum[lane] = w;
    }
    __syncthreads();
    int excl = (wid ? wsum[wid - 1] : 0) + x - tsum;
    int4 o4;
    o4.x = excl;
    o4.y = o4.x + v.x;
    o4.z = o4.y + v.y;
    o4.w = o4.z + v.z;
    if (f < n4) {
        if (f * 4 + 3 < n) ((int4*)g_off)[f] = o4;
        else {
            if (f * 4 + 0 < n) g_off[f * 4 + 0] = o4.x;
            if (f * 4 + 1 < n) g_off[f * 4 + 1] = o4.y;
            if (f * 4 + 2 < n) g_off[f * 4 + 2] = o4.z;
        }
    }
    if (tid == 0) g_bsum[blockIdx.x] = wsum[31];
}

__global__ void scan_add(int n) {
    __shared__ int s_add;
    int tid = threadIdx.x;
    if (tid < 32) {
        int v = (tid < (int)blockIdx.x) ? g_bsum[tid] : 0;
#pragma unroll
        for (int o = 16; o; o >>= 1) v += __shfl_xor_sync(0xffffffffu, v, o);
        if (tid == 0) s_add = v;
    }
    __syncthreads();
    int add = s_add;
    int n4 = (n + 3) >> 2;
    int f = blockIdx.x * 1024 + tid;
    if (f >= n4) return;
    if (f * 4 + 3 < n) {
        int4 o = ((const int4*)g_off)[f];
        o.x += add; o.y += add; o.z += add; o.w += add;
        ((int4*)g_off)[f] = o;
        ((int4*)g_cur)[f] = o;
    } else {
#pragma unroll
        for (int j = 0; j < 3; j++)
            if (f * 4 + j < n) {
                int o = g_off[f * 4 + j] + add;
                g_off[f * 4 + j] = o;
                g_cur[f * 4 + j] = o;
            }
    }
}

__global__ void csr_fill(const int* __restrict__ ei, int E) {
    int e = blockIdx.x * blockDim.x + threadIdx.x;
    if (e >= E) return;
    int s = ei[e];
    int d = ei[E + e];
    int pos = atomicAdd(&g_cur[d], 1);
    g_srcl[pos] = s;
}

// ---------------- fused gather: softmax + aggregate + bias + residual + LN ----------------
__global__ void gat_gather(const float* __restrict__ x,
                           const float* __restrict__ bias,
                           const float* __restrict__ gamma,
                           const float* __restrict__ beta, int n) {
    int warp = (blockIdx.x * blockDim.x + threadIdx.x) >> 5;
    int lane = threadIdx.x & 31;
    if (warp >= n) return;
    const int i  = warp;
    const int h0 = lane >> 3;
    const int h1 = 4 + h0;

    float4 acc0 = {0.f, 0.f, 0.f, 0.f};
    float4 acc1 = {0.f, 0.f, 0.f, 0.f};
    float  den  = 0.f;
    float  adst = (lane < 8) ? g_adst[i * 8 + lane] : 0.f;

    const int start = g_off[i];
    const int deg   = g_deg[i];
    const int* sl   = g_srcl + start;
    const int ng    = deg >> 2;

    if (ng > 0) {
        int cs0 = sl[0], cs1 = sl[1], cs2 = sl[2], cs3 = sl[3];
        for (int gi = 1; gi <= ng; gi++) {
            int ns0 = 0, ns1 = 0, ns2 = 0, ns3 = 0;
            if (gi < ng) {
                int b = gi * 4;
                ns0 = sl[b]; ns1 = sl[b + 1]; ns2 = sl[b + 2]; ns3 = sl[b + 3];
            }
            float ex0 = 0.f, ex1 = 0.f, ex2 = 0.f, ex3 = 0.f;
            if (lane < 8) {
                float l0 = g_asrc[cs0 * 8 + lane];
                float l1 = g_asrc[cs1 * 8 + lane];
                float l2 = g_asrc[cs2 * 8 + lane];
                float l3 = g_asrc[cs3 * 8 + lane];
                ex0 = __expf(leaky(l0 + adst));
                ex1 = __expf(leaky(l1 + adst));
                ex2 = __expf(leaky(l2 + adst));
                ex3 = __expf(leaky(l3 + adst));
                den += (ex0 + ex1) + (ex2 + ex3);
            }
            const float4* xs0 = (const float4*)(g_xp + cs0 * 256);
            const float4* xs1 = (const float4*)(g_xp + cs1 * 256);
            const float4* xs2 = (const float4*)(g_xp + cs2 * 256);
            const float4* xs3 = (const float4*)(g_xp + cs3 * 256);
            float4 u0 = xs0[lane], u1 = xs0[32 + lane];
            float4 w0 = xs1[lane], w1 = xs1[32 + lane];
            float4 y0 = xs2[lane], y1 = xs2[32 + lane];
            float4 z0 = xs3[lane], z1 = xs3[32 + lane];
            float a00 = __shfl_sync(0xffffffffu, ex0, h0);
            float a01 = __shfl_sync(0xffffffffu, ex0, h1);
            float a10 = __shfl_sync(0xffffffffu, ex1, h0);
            float a11 = __shfl_sync(0xffffffffu, ex1, h1);
            float a20 = __shfl_sync(0xffffffffu, ex2, h0);
            float a21 = __shfl_sync(0xffffffffu, ex2, h1);
            float a30 = __shfl_sync(0xffffffffu, ex3, h0);
            float a31 = __shfl_sync(0xffffffffu, ex3, h1);
            acc0.x = fmaf(a00, u0.x, acc0.x); acc0.y = fmaf(a00, u0.y, acc0.y);
            acc0.z = fmaf(a00, u0.z, acc0.z); acc0.w = fmaf(a00, u0.w, acc0.w);
            acc1.x = fmaf(a01, u1.x, acc1.x); acc1.y = fmaf(a01, u1.y, acc1.y);
            acc1.z = fmaf(a01, u1.z, acc1.z); acc1.w = fmaf(a01, u1.w, acc1.w);
            acc0.x = fmaf(a10, w0.x, acc0.x); acc0.y = fmaf(a10, w0.y, acc0.y);
            acc0.z = fmaf(a10, w0.z, acc0.z); acc0.w = fmaf(a10, w0.w, acc0.w);
            acc1.x = fmaf(a11, w1.x, acc1.x); acc1.y = fmaf(a11, w1.y, acc1.y);
            acc1.z = fmaf(a11, w1.z, acc1.z); acc1.w = fmaf(a11, w1.w, acc1.w);
            acc0.x = fmaf(a20, y0.x, acc0.x); acc0.y = fmaf(a20, y0.y, acc0.y);
            acc0.z = fmaf(a20, y0.z, acc0.z); acc0.w = fmaf(a20, y0.w, acc0.w);
            acc1.x = fmaf(a21, y1.x, acc1.x); acc1.y = fmaf(a21, y1.y, acc1.y);
            acc1.z = fmaf(a21, y1.z, acc1.z); acc1.w = fmaf(a21, y1.w, acc1.w);
            acc0.x = fmaf(a30, z0.x, acc0.x); acc0.y = fmaf(a30, z0.y, acc0.y);
            acc0.z = fmaf(a30, z0.z, acc0.z); acc0.w = fmaf(a30, z0.w, acc0.w);
            acc1.x = fmaf(a31, z1.x, acc1.x); acc1.y = fmaf(a31, z1.y, acc1.y);
            acc1.z = fmaf(a31, z1.z, acc1.z); acc1.w = fmaf(a31, z1.w, acc1.w);
            cs0 = ns0; cs1 = ns1; cs2 = ns2; cs3 = ns3;
        }
    }
    for (int e = ng * 4; e < deg; e++) {
        int s = sl[e];
        float ex = 0.f;
        if (lane < 8) {
            ex = __expf(leaky(g_asrc[s * 8 + lane] + adst));
            den += ex;
        }
        float e0 = __shfl_sync(0xffffffffu, ex, h0);
        float e1 = __shfl_sync(0xffffffffu, ex, h1);
        const float4* xs = (const float4*)(g_xp + s * 256);
        float4 v0 = xs[lane], v1 = xs[32 + lane];
        acc0.x = fmaf(e0, v0.x, acc0.x); acc0.y = fmaf(e0, v0.y, acc0.y);
        acc0.z = fmaf(e0, v0.z, acc0.z); acc0.w = fmaf(e0, v0.w, acc0.w);
        acc1.x = fmaf(e1, v1.x, acc1.x); acc1.y = fmaf(e1, v1.y, acc1.y);
        acc1.z = fmaf(e1, v1.z, acc1.z); acc1.w = fmaf(e1, v1.w, acc1.w);
    }

    // self loop
    {
        float ex = 0.f;
        if (lane < 8) {
            ex = __expf(leaky(g_asrc[i * 8 + lane] + adst));
            den += ex;
        }
        float e0 = __shfl_sync(0xffffffffu, ex, h0);
        float e1 = __shfl_sync(0xffffffffu, ex, h1);
        const float4* xs = (const float4*)(g_xp + i * 256);
        float4 v0 = xs[lane], v1 = xs[32 + lane];
        acc0.x = fmaf(e0, v0.x, acc0.x); acc0.y = fmaf(e0, v0.y, acc0.y);
        acc0.z = fmaf(e0, v0.z, acc0.z); acc0.w = fmaf(e0, v0.w, acc0.w);
        acc1.x = fmaf(e1, v1.x, acc1.x); acc1.y = fmaf(e1, v1.y, acc1.y);
        acc1.z = fmaf(e1, v1.z, acc1.z); acc1.w = fmaf(e1, v1.w, acc1.w);
    }

    float inv0 = 1.f / (__shfl_sync(0xffffffffu, den, h0) + 1e-16f);
    float inv1 = 1.f / (__shfl_sync(0xffffffffu, den, h1) + 1e-16f);

    const float4* xr = (const float4*)(x + i * 256);
    const float4* bi = (const float4*)bias;
    float4 xv0 = xr[lane], xv1 = xr[32 + lane];
    float4 b0  = bi[lane], b1  = bi[32 + lane];
    float r[8];
    r[0] = fmaf(acc0.x, inv0, b0.x) + xv0.x;
    r[1] = fmaf(acc0.y, inv0, b0.y) + xv0.y;
    r[2] = fmaf(acc0.z, inv0, b0.z) + xv0.z;
    r[3] = fmaf(acc0.w, inv0, b0.w) + xv0.w;
    r[4] = fmaf(acc1.x, inv1, b1.x) + xv1.x;
    r[5] = fmaf(acc1.y, inv1, b1.y) + xv1.y;
    r[6] = fmaf(acc1.z, inv1, b1.z) + xv1.z;
    r[7] = fmaf(acc1.w, inv1, b1.w) + xv1.w;

    float s = r[0] + r[1] + r[2] + r[3] + r[4] + r[5] + r[6] + r[7];
#pragma unroll
    for (int o = 16; o; o >>= 1) s += __shfl_xor_sync(0xffffffffu, s, o);
    float mu = s * (1.0f / 256.0f);
    float c[8], v2 = 0.f;
#pragma unroll
    for (int k = 0; k < 8; k++) { c[k] = r[k] - mu; v2 = fmaf(c[k], c[k], v2); }
#pragma unroll
    for (int o = 16; o; o >>= 1) v2 += __shfl_xor_sync(0xffffffffu, v2, o);
    float rstd = rsqrtf(v2 * (1.0f / 256.0f) + 1e-5f);

    const float4* gp = (const float4*)gamma;
    const float4* bp = (const float4*)beta;
    float4 g0 = gp[lane], g1 = gp[32 + lane];
    float4 p0 = bp[lane], p1 = bp[32 + lane];
    float4 o0, o1;
    o0.x = fmaf(c[0] * rstd, g0.x, p0.x);
    o0.y = fmaf(c[1] * rstd, g0.y, p0.y);
    o0.z = fmaf(c[2] * rstd, g0.z, p0.z);
    o0.w = fmaf(c[3] * rstd, g0.w, p0.w);
    o1.x = fmaf(c[4] * rstd, g1.x, p1.x);
    o1.y = fmaf(c[5] * rstd, g1.y, p1.y);
    o1.z = fmaf(c[6] * rstd, g1.z, p1.z);
    o1.w = fmaf(c[7] * rstd, g1.w, p1.w);
    float4* out = (float4*)(g_hn + i * 256);
    out[lane]      = o0;
    out[32 + lane] = o1;
}

// ---------------- launch ----------------
extern "C" void kernel_launch(void* const* d_in, const int* in_sizes, int n_in,
                              void* d_out, int out_size) {
    const float* x       = (const float*)d_in[0];
    const int*   ei      = (const int*)d_in[1];
    const float* W       = (const float*)d_in[3];
    const float* att_src = (const float*)d_in[4];
    const float* att_dst = (const float*)d_in[5];
    const float* bias    = (const float*)d_in[6];
    const float* ln_g    = (const float*)d_in[7];
    const float* ln_b    = (const float*)d_in[8];
    const float* W1      = (const float*)d_in[9];
    const float* b1      = (const float*)d_in[10];
    const float* W2      = (const float*)d_in[11];
    const float* b2      = (const float*)d_in[12];

    const int n = in_sizes[0] / DD;
    const int E = in_sizes[1] / 2;

    float *xp, *hn, *hid;
    int   *deg;
    cudaGetSymbolAddress((void**)&xp,  g_xp);
    cudaGetSymbolAddress((void**)&hn,  g_hn);
    cudaGetSymbolAddress((void**)&hid, g_hid);
    cudaGetSymbolAddress((void**)&deg, g_deg);

    static cudaStream_t s2 = nullptr;
    static cudaEvent_t ev_fork = nullptr, ev_join = nullptr;
    if (!s2) {
        cudaStreamCreateWithFlags(&s2, cudaStreamNonBlocking);
        cudaEventCreateWithFlags(&ev_fork, cudaEventDisableTiming);
        cudaEventCreateWithFlags(&ev_join, cudaEventDisableTiming);
    }

    dim3 gg((n + 127) / 128, 4);
    const int n4 = (n + 3) >> 2;
    const int nscan = (n4 + 1023) / 1024;

    cudaEventRecord(ev_fork, 0);
    cudaStreamWaitEvent(s2, ev_fork, 0);

    cudaMemsetAsync(deg, 0, n * sizeof(int), s2);
    deg_count<<<(E + 511) / 512, 512, 0, s2>>>(ei, E);
    scan_part<<<nscan, 1024, 0, s2>>>(n);
    scan_add <<<nscan, 1024, 0, s2>>>(n);
    csr_fill <<<(E + 255) / 256, 256, 0, s2>>>(ei, E);
    cudaEventRecord(ev_join, s2);

    gemm_tc<false, false><<<gg, 256>>>(x, W, nullptr, xp, n);
    node_att<<<(n * 32 + 255) / 256, 256>>>(att_src, att_dst, n);

    cudaStreamWaitEvent(0, ev_join, 0);

    gat_gather<<<(n * 32 + 255) / 256, 256>>>(x, bias, ln_g, ln_b, n);
    gemm_tc<true,  true><<<gg, 256>>>(hn,  W1, b1, hid, n);
    gemm_tc<false, true><<<gg, 256>>>(hid, W2, b2, (float*)d_out, n);
}

// round 9
// speedup vs baseline: 1.0907x; 1.0907x over previous
#include <cuda_runtime.h>
#include <cuda_bf16.h>

// ---------------- problem constants ----------------
#define DD 256
#define HH 8
#define N_MAX 50048
#define E_MAX 800000
#define NEG_SLOPE 0.2f

// ---------------- device scratch ----------------
__device__ __align__(256) unsigned g_xpb [N_MAX * 128];  // x@W as bf16x2 (128 words/row)
__device__ __align__(256) float    g_asrc[N_MAX * HH];
__device__ __align__(256) float    g_adst[N_MAX * HH];
__device__ __align__(256) float    g_hn  [N_MAX * DD];
__device__ __align__(256) float    g_hid [N_MAX * DD];
__device__ __align__(256) int      g_deg [N_MAX];
__device__ __align__(256) int      g_off [N_MAX];
__device__ __align__(256) int      g_cur [N_MAX];
__device__ __align__(256) int      g_srcl[E_MAX];
__device__ int g_bsum[64];

__device__ __forceinline__ float leaky(float v) {
    return v > 0.f ? v : NEG_SLOPE * v;
}

// bf16x2 word -> two floats (low half = first channel)
__device__ __forceinline__ float bfl(unsigned w) { return __uint_as_float(w << 16); }
__device__ __forceinline__ float bfh(unsigned w) { return __uint_as_float(w & 0xffff0000u); }

// ---------------- bf16-split helpers ----------------
__device__ __forceinline__ unsigned pack_hi(float x, float y) {
    unsigned r;
    asm("prmt.b32 %0, %1, %2, 0x7632;"
        : "=r"(r) : "r"(__float_as_uint(x)), "r"(__float_as_uint(y)));
    return r;
}
__device__ __forceinline__ unsigned pack_lo(float x, float y) {
    float hx = __uint_as_float(__float_as_uint(x) & 0xffff0000u);
    float hy = __uint_as_float(__float_as_uint(y) & 0xffff0000u);
    float lx = x - hx, ly = y - hy;
    unsigned r;
    asm("cvt.rn.bf16x2.f32 %0, %1, %2;" : "=r"(r) : "f"(ly), "f"(lx));
    return r;
}
__device__ __forceinline__ unsigned pack_rn(float x, float y) {
    unsigned r;
    asm("cvt.rn.bf16x2.f32 %0, %1, %2;" : "=r"(r) : "f"(y), "f"(x));
    return r;
}

__device__ __forceinline__ void mma16(float* c, const unsigned* a, const unsigned* b) {
    asm("mma.sync.aligned.m16n8k16.row.col.f32.bf16.bf16.f32 "
        "{%0,%1,%2,%3}, {%4,%5,%6,%7}, {%8,%9}, {%0,%1,%2,%3};"
        : "+f"(c[0]), "+f"(c[1]), "+f"(c[2]), "+f"(c[3])
        : "r"(a[0]), "r"(a[1]), "r"(a[2]), "r"(a[3]), "r"(b[0]), "r"(b[1]));
}

// ---------------- tensor-core GEMM (3xBF16 split, m16n8k16) ----------------
// block: 256 threads = 8 warps (4m x 2n), tile 128 x 64; warp tile 32 x 32
// ATTOUT: write bf16x2 to g_xpb + fused per-head attention logits (fp32 accs)
template <bool RELU, bool BIAS, bool ATTOUT>
__global__ __launch_bounds__(256)
void gemm_tc(const float* __restrict__ A, const float* __restrict__ B,
             const float* __restrict__ bias, float* __restrict__ C,
             const float* __restrict__ att_s, const float* __restrict__ att_d,
             int M) {
    __shared__ float As[128][36];
    __shared__ float Bs[32][68];
    const int tid  = threadIdx.x;
    const int lane = tid & 31;
    const int warp = tid >> 5;
    const int wm   = warp & 3;
    const int wn   = warp >> 2;
    const int brow = blockIdx.x * 128;
    const int bcol = blockIdx.y * 64;
    const int q    = lane >> 2;
    const int tq   = lane & 3;

    const int ar0 = tid >> 3;
    const int ac4 = (tid & 7) * 4;
    const int br  = tid >> 4;
    const int bc4 = (tid & 15) * 4;

    float acc[2][4][4];
#pragma unroll
    for (int mt = 0; mt < 2; mt++)
#pragma unroll
        for (int nt = 0; nt < 4; nt++)
#pragma unroll
            for (int k = 0; k < 4; k++) acc[mt][nt][k] = 0.f;

    float4 pa[4], pb[2];

#pragma unroll
    for (int j = 0; j < 4; j++) {
        int gr = brow + ar0 + 32 * j;
        pa[j] = (gr < M) ? *(const float4*)(A + gr * 256 + ac4)
                         : make_float4(0.f, 0.f, 0.f, 0.f);
    }
    pb[0] = *(const float4*)(B + br * 256 + bcol + bc4);
    pb[1] = *(const float4*)(B + (16 + br) * 256 + bcol + bc4);
#pragma unroll
    for (int j = 0; j < 4; j++) *(float4*)&As[ar0 + 32 * j][ac4] = pa[j];
    *(float4*)&Bs[br][bc4]      = pb[0];
    *(float4*)&Bs[16 + br][bc4] = pb[1];
    __syncthreads();

    for (int k0 = 0; k0 < 8; k0++) {
        if (k0 < 7) {
            int kb = (k0 + 1) * 32;
#pragma unroll
            for (int j = 0; j < 4; j++) {
                int gr = brow + ar0 + 32 * j;
                pa[j] = (gr < M) ? *(const float4*)(A + gr * 256 + kb + ac4)
                                 : make_float4(0.f, 0.f, 0.f, 0.f);
            }
            pb[0] = *(const float4*)(B + (kb + br) * 256 + bcol + bc4);
            pb[1] = *(const float4*)(B + (kb + 16 + br) * 256 + bcol + bc4);
        }

#pragma unroll
        for (int kk = 0; kk < 2; kk++) {
            const int kb = kk * 16;
            unsigned bh[4][2], bl[4][2];
#pragma unroll
            for (int nt = 0; nt < 4; nt++) {
                int col = wn * 32 + nt * 8 + q;
                int r0  = kb + 2 * tq;
                float x0 = Bs[r0][col],     x1 = Bs[r0 + 1][col];
                float x2 = Bs[r0 + 8][col], x3 = Bs[r0 + 9][col];
                bh[nt][0] = pack_hi(x0, x1); bl[nt][0] = pack_lo(x0, x1);
                bh[nt][1] = pack_hi(x2, x3); bl[nt][1] = pack_lo(x2, x3);
            }
            unsigned ah[2][4], al[2][4];
#pragma unroll
            for (int mt = 0; mt < 2; mt++) {
                int r0 = wm * 32 + mt * 16 + q;
                int c  = kb + 2 * tq;
                float2 p0 = *(float2*)&As[r0][c];
                float2 p1 = *(float2*)&As[r0 + 8][c];
                float2 p2 = *(float2*)&As[r0][c + 8];
                float2 p3 = *(float2*)&As[r0 + 8][c + 8];
                ah[mt][0] = pack_hi(p0.x, p0.y); al[mt][0] = pack_lo(p0.x, p0.y);
                ah[mt][1] = pack_hi(p1.x, p1.y); al[mt][1] = pack_lo(p1.x, p1.y);
                ah[mt][2] = pack_hi(p2.x, p2.y); al[mt][2] = pack_lo(p2.x, p2.y);
                ah[mt][3] = pack_hi(p3.x, p3.y); al[mt][3] = pack_lo(p3.x, p3.y);
            }
#pragma unroll
            for (int mt = 0; mt < 2; mt++)
#pragma unroll
                for (int nt = 0; nt < 4; nt++) {
                    mma16(acc[mt][nt], al[mt], bh[nt]);
                    mma16(acc[mt][nt], ah[mt], bl[nt]);
                    mma16(acc[mt][nt], ah[mt], bh[nt]);
                }
        }
        __syncthreads();
        if (k0 < 7) {
#pragma unroll
            for (int j = 0; j < 4; j++) *(float4*)&As[ar0 + 32 * j][ac4] = pa[j];
            *(float4*)&Bs[br][bc4]      = pb[0];
            *(float4*)&Bs[16 + br][bc4] = pb[1];
            __syncthreads();
        }
    }

    if (ATTOUT) {
        // head for this warp's 8 columns (all within one head)
        const int h = 2 * blockIdx.y + wn;
        // att vector entries for this thread's columns (channel within head)
        float avs[4][2], avd[4][2];
#pragma unroll
        for (int nt = 0; nt < 4; nt++) {
            int ch = nt * 8 + 2 * tq;
            avs[nt][0] = att_s[h * 32 + ch];     avs[nt][1] = att_s[h * 32 + ch + 1];
            avd[nt][0] = att_d[h * 32 + ch];     avd[nt][1] = att_d[h * 32 + ch + 1];
        }
#pragma unroll
        for (int mt = 0; mt < 2; mt++) {
            int gr0 = brow + wm * 32 + mt * 16 + q;
            float ps0 = 0.f, pd0 = 0.f, ps1 = 0.f, pd1 = 0.f;
#pragma unroll
            for (int nt = 0; nt < 4; nt++) {
                int gc = bcol + wn * 32 + nt * 8 + 2 * tq;
                // bf16x2 output word (channels gc, gc+1)
                unsigned w0 = pack_rn(acc[mt][nt][0], acc[mt][nt][1]);
                unsigned w1 = pack_rn(acc[mt][nt][2], acc[mt][nt][3]);
                if (gr0 < M)     g_xpb[gr0 * 128 + (gc >> 1)]       = w0;
                if (gr0 + 8 < M) g_xpb[(gr0 + 8) * 128 + (gc >> 1)] = w1;
                // fp32 attention partials
                ps0 = fmaf(acc[mt][nt][0], avs[nt][0], fmaf(acc[mt][nt][1], avs[nt][1], ps0));
                pd0 = fmaf(acc[mt][nt][0], avd[nt][0], fmaf(acc[mt][nt][1], avd[nt][1], pd0));
                ps1 = fmaf(acc[mt][nt][2], avs[nt][0], fmaf(acc[mt][nt][3], avs[nt][1], ps1));
                pd1 = fmaf(acc[mt][nt][2], avd[nt][0], fmaf(acc[mt][nt][3], avd[nt][1], pd1));
            }
            // reduce over the 4 tq lanes (same rows, different columns)
            ps0 += __shfl_xor_sync(0xffffffffu, ps0, 1);
            ps0 += __shfl_xor_sync(0xffffffffu, ps0, 2);
            pd0 += __shfl_xor_sync(0xffffffffu, pd0, 1);
            pd0 += __shfl_xor_sync(0xffffffffu, pd0, 2);
            ps1 += __shfl_xor_sync(0xffffffffu, ps1, 1);
            ps1 += __shfl_xor_sync(0xffffffffu, ps1, 2);
            pd1 += __shfl_xor_sync(0xffffffffu, pd1, 1);
            pd1 += __shfl_xor_sync(0xffffffffu, pd1, 2);
            if (tq == 0) {
                if (gr0 < M)     { g_asrc[gr0 * 8 + h] = ps0;       g_adst[gr0 * 8 + h] = pd0; }
                if (gr0 + 8 < M) { g_asrc[(gr0 + 8) * 8 + h] = ps1; g_adst[(gr0 + 8) * 8 + h] = pd1; }
            }
        }
        return;
    }

    // fp32 epilogue
#pragma unroll
    for (int mt = 0; mt < 2; mt++) {
        int gr0 = brow + wm * 32 + mt * 16 + q;
#pragma unroll
        for (int nt = 0; nt < 4; nt++) {
            int gc = bcol + wn * 32 + nt * 8 + 2 * tq;
            float bx = 0.f, by = 0.f;
            if (BIAS) { bx = bias[gc]; by = bias[gc + 1]; }
            float2 v0 = make_float2(acc[mt][nt][0] + bx, acc[mt][nt][1] + by);
            float2 v1 = make_float2(acc[mt][nt][2] + bx, acc[mt][nt][3] + by);
            if (RELU) {
                v0.x = fmaxf(v0.x, 0.f); v0.y = fmaxf(v0.y, 0.f);
                v1.x = fmaxf(v1.x, 0.f); v1.y = fmaxf(v1.y, 0.f);
            }
            if (gr0 < M)     *(float2*)(C + gr0 * 256 + gc)       = v0;
            if (gr0 + 8 < M) *(float2*)(C + (gr0 + 8) * 256 + gc) = v1;
        }
    }
}

// ---------------- CSR build ----------------
__global__ void deg_count(const int* __restrict__ ei, int E) {
    int e = blockIdx.x * blockDim.x + threadIdx.x;
    if (e >= E) return;
    atomicAdd(&g_deg[ei[E + e]], 1);
}

__global__ void scan_part(int n) {
    __shared__ int wsum[32];
    int tid = threadIdx.x, lane = tid & 31, wid = tid >> 5;
    int n4 = (n + 3) >> 2;
    int f = blockIdx.x * 1024 + tid;
    int4 v = make_int4(0, 0, 0, 0);
    if (f < n4) {
        if (f * 4 + 3 < n) v = ((const int4*)g_deg)[f];
        else {
            if (f * 4 + 0 < n) v.x = g_deg[f * 4 + 0];
            if (f * 4 + 1 < n) v.y = g_deg[f * 4 + 1];
            if (f * 4 + 2 < n) v.z = g_deg[f * 4 + 2];
        }
    }
    int tsum = v.x + v.y + v.z + v.w;
    int x = tsum;
#pragma unroll
    for (int o = 1; o < 32; o <<= 1) {
        int t = __shfl_up_sync(0xffffffffu, x, o);
        if (lane >= o) x += t;
    }
    if (lane == 31) wsum[wid] = x;
    __syncthreads();
    if (wid == 0) {
        int w = wsum[lane];
#pragma unroll
        for (int o = 1; o < 32; o <<= 1) {
            int t = __shfl_up_sync(0xffffffffu, w, o);
            if (lane >= o) w += t;
        }
        wsum[lane] = w;
    }
    __syncthreads();
    int excl = (wid ? wsum[wid - 1] : 0) + x - tsum;
    int4 o4;
    o4.x = excl;
    o4.y = o4.x + v.x;
    o4.z = o4.y + v.y;
    o4.w = o4.z + v.z;
    if (f < n4) {
        if (f * 4 + 3 < n) ((int4*)g_off)[f] = o4;
        else {
            if (f * 4 + 0 < n) g_off[f * 4 + 0] = o4.x;
            if (f * 4 + 1 < n) g_off[f * 4 + 1] = o4.y;
            if (f * 4 + 2 < n) g_off[f * 4 + 2] = o4.z;
        }
    }
    if (tid == 0) g_bsum[blockIdx.x] = wsum[31];
}

__global__ void scan_add(int n) {
    __shared__ int s_add;
    int tid = threadIdx.x;
    if (tid < 32) {
        int v = (tid < (int)blockIdx.x) ? g_bsum[tid] : 0;
#pragma unroll
        for (int o = 16; o; o >>= 1) v += __shfl_xor_sync(0xffffffffu, v, o);
        if (tid == 0) s_add = v;
    }
    __syncthreads();
    int add = s_add;
    int n4 = (n + 3) >> 2;
    int f = blockIdx.x * 1024 + tid;
    if (f >= n4) return;
    if (f * 4 + 3 < n) {
        int4 o = ((const int4*)g_off)[f];
        o.x += add; o.y += add; o.z += add; o.w += add;
        ((int4*)g_off)[f] = o;
        ((int4*)g_cur)[f] = o;
    } else {
#pragma unroll
        for (int j = 0; j < 3; j++)
            if (f * 4 + j < n) {
                int o = g_off[f * 4 + j] + add;
                g_off[f * 4 + j] = o;
                g_cur[f * 4 + j] = o;
            }
    }
}

__global__ void csr_fill(const int* __restrict__ ei, int E) {
    int e = blockIdx.x * blockDim.x + threadIdx.x;
    if (e >= E) return;
    int s = ei[e];
    int d = ei[E + e];
    int pos = atomicAdd(&g_cur[d], 1);
    g_srcl[pos] = s;
}

// ---------------- fused gather (bf16 payload): softmax + aggregate + bias + residual + LN ----------------
__global__ void gat_gather(const float* __restrict__ x,
                           const float* __restrict__ bias,
                           const float* __restrict__ gamma,
                           const float* __restrict__ beta, int n) {
    int warp = (blockIdx.x * blockDim.x + threadIdx.x) >> 5;
    int lane = threadIdx.x & 31;
    if (warp >= n) return;
    const int i  = warp;
    const int h0 = lane >> 3;
    const int h1 = 4 + h0;

    float4 acc0 = {0.f, 0.f, 0.f, 0.f};
    float4 acc1 = {0.f, 0.f, 0.f, 0.f};
    float  den  = 0.f;
    float  adst = (lane < 8) ? g_adst[i * 8 + lane] : 0.f;

    const int start = g_off[i];
    const int deg   = g_deg[i];
    const int* sl   = g_srcl + start;

    int e = 0;
    for (; e + 4 <= deg; e += 4) {
        int s0 = sl[e], s1 = sl[e + 1], s2 = sl[e + 2], s3 = sl[e + 3];
        float ex0 = 0.f, ex1 = 0.f, ex2 = 0.f, ex3 = 0.f;
        if (lane < 8) {
            float l0 = g_asrc[s0 * 8 + lane];
            float l1 = g_asrc[s1 * 8 + lane];
            float l2 = g_asrc[s2 * 8 + lane];
            float l3 = g_asrc[s3 * 8 + lane];
            ex0 = __expf(leaky(l0 + adst));
            ex1 = __expf(leaky(l1 + adst));
            ex2 = __expf(leaky(l2 + adst));
            ex3 = __expf(leaky(l3 + adst));
            den += (ex0 + ex1) + (ex2 + ex3);
        }
        const uint2* p0 = (const uint2*)(g_xpb + s0 * 128);
        const uint2* p1 = (const uint2*)(g_xpb + s1 * 128);
        const uint2* p2 = (const uint2*)(g_xpb + s2 * 128);
        const uint2* p3 = (const uint2*)(g_xpb + s3 * 128);
        uint2 u0 = p0[lane], u1 = p0[32 + lane];
        uint2 w0 = p1[lane], w1 = p1[32 + lane];
        uint2 y0 = p2[lane], y1 = p2[32 + lane];
        uint2 z0 = p3[lane], z1 = p3[32 + lane];
        float a00 = __shfl_sync(0xffffffffu, ex0, h0);
        float a01 = __shfl_sync(0xffffffffu, ex0, h1);
        float a10 = __shfl_sync(0xffffffffu, ex1, h0);
        float a11 = __shfl_sync(0xffffffffu, ex1, h1);
        float a20 = __shfl_sync(0xffffffffu, ex2, h0);
        float a21 = __shfl_sync(0xffffffffu, ex2, h1);
        float a30 = __shfl_sync(0xffffffffu, ex3, h0);
        float a31 = __shfl_sync(0xffffffffu, ex3, h1);
        acc0.x = fmaf(a00, bfl(u0.x), acc0.x); acc0.y = fmaf(a00, bfh(u0.x), acc0.y);
        acc0.z = fmaf(a00, bfl(u0.y), acc0.z); acc0.w = fmaf(a00, bfh(u0.y), acc0.w);
        acc1.x = fmaf(a01, bfl(u1.x), acc1.x); acc1.y = fmaf(a01, bfh(u1.x), acc1.y);
        acc1.z = fmaf(a01, bfl(u1.y), acc1.z); acc1.w = fmaf(a01, bfh(u1.y), acc1.w);
        acc0.x = fmaf(a10, bfl(w0.x), acc0.x); acc0.y = fmaf(a10, bfh(w0.x), acc0.y);
        acc0.z = fmaf(a10, bfl(w0.y), acc0.z); acc0.w = fmaf(a10, bfh(w0.y), acc0.w);
        acc1.x = fmaf(a11, bfl(w1.x), acc1.x); acc1.y = fmaf(a11, bfh(w1.x), acc1.y);
        acc1.z = fmaf(a11, bfl(w1.y), acc1.z); acc1.w = fmaf(a11, bfh(w1.y), acc1.w);
        acc0.x = fmaf(a20, bfl(y0.x), acc0.x); acc0.y = fmaf(a20, bfh(y0.x), acc0.y);
        acc0.z = fmaf(a20, bfl(y0.y), acc0.z); acc0.w = fmaf(a20, bfh(y0.y), acc0.w);
        acc1.x = fmaf(a21, bfl(y1.x), acc1.x); acc1.y = fmaf(a21, bfh(y1.x), acc1.y);
        acc1.z = fmaf(a21, bfl(y1.y), acc1.z); acc1.w = fmaf(a21, bfh(y1.y), acc1.w);
        acc0.x = fmaf(a30, bfl(z0.x), acc0.x); acc0.y = fmaf(a30, bfh(z0.x), acc0.y);
        acc0.z = fmaf(a30, bfl(z0.y), acc0.z); acc0.w = fmaf(a30, bfh(z0.y), acc0.w);
        acc1.x = fmaf(a31, bfl(z1.x), acc1.x); acc1.y = fmaf(a31, bfh(z1.x), acc1.y);
        acc1.z = fmaf(a31, bfl(z1.y), acc1.z); acc1.w = fmaf(a31, bfh(z1.y), acc1.w);
    }
    for (; e < deg; e++) {
        int s = sl[e];
        float ex = 0.f;
        if (lane < 8) {
            ex = __expf(leaky(g_asrc[s * 8 + lane] + adst));
            den += ex;
        }
        float e0 = __shfl_sync(0xffffffffu, ex, h0);
        float e1 = __shfl_sync(0xffffffffu, ex, h1);
        const uint2* p = (const uint2*)(g_xpb + s * 128);
        uint2 v0 = p[lane], v1 = p[32 + lane];
        acc0.x = fmaf(e0, bfl(v0.x), acc0.x); acc0.y = fmaf(e0, bfh(v0.x), acc0.y);
        acc0.z = fmaf(e0, bfl(v0.y), acc0.z); acc0.w = fmaf(e0, bfh(v0.y), acc0.w);
        acc1.x = fmaf(e1, bfl(v1.x), acc1.x); acc1.y = fmaf(e1, bfh(v1.x), acc1.y);
        acc1.z = fmaf(e1, bfl(v1.y), acc1.z); acc1.w = fmaf(e1, bfh(v1.y), acc1.w);
    }

    // self loop
    {
        float ex = 0.f;
        if (lane < 8) {
            ex = __expf(leaky(g_asrc[i * 8 + lane] + adst));
            den += ex;
        }
        float e0 = __shfl_sync(0xffffffffu, ex, h0);
        float e1 = __shfl_sync(0xffffffffu, ex, h1);
        const uint2* p = (const uint2*)(g_xpb + i * 128);
        uint2 v0 = p[lane], v1 = p[32 + lane];
        acc0.x = fmaf(e0, bfl(v0.x), acc0.x); acc0.y = fmaf(e0, bfh(v0.x), acc0.y);
        acc0.z = fmaf(e0, bfl(v0.y), acc0.z); acc0.w = fmaf(e0, bfh(v0.y), acc0.w);
        acc1.x = fmaf(e1, bfl(v1.x), acc1.x); acc1.y = fmaf(e1, bfh(v1.x), acc1.y);
        acc1.z = fmaf(e1, bfl(v1.y), acc1.z); acc1.w = fmaf(e1, bfh(v1.y), acc1.w);
    }

    float inv0 = 1.f / (__shfl_sync(0xffffffffu, den, h0) + 1e-16f);
    float inv1 = 1.f / (__shfl_sync(0xffffffffu, den, h1) + 1e-16f);

    const float4* xr = (const float4*)(x + i * 256);
    const float4* bi = (const float4*)bias;
    float4 xv0 = xr[lane], xv1 = xr[32 + lane];
    float4 b0  = bi[lane], b1  = bi[32 + lane];
    float r[8];
    r[0] = fmaf(acc0.x, inv0, b0.x) + xv0.x;
    r[1] = fmaf(acc0.y, inv0, b0.y) + xv0.y;
    r[2] = fmaf(acc0.z, inv0, b0.z) + xv0.z;
    r[3] = fmaf(acc0.w, inv0, b0.w) + xv0.w;
    r[4] = fmaf(acc1.x, inv1, b1.x) + xv1.x;
    r[5] = fmaf(acc1.y, inv1, b1.y) + xv1.y;
    r[6] = fmaf(acc1.z, inv1, b1.z) + xv1.z;
    r[7] = fmaf(acc1.w, inv1, b1.w) + xv1.w;

    float s = r[0] + r[1] + r[2] + r[3] + r[4] + r[5] + r[6] + r[7];
#pragma unroll
    for (int o = 16; o; o >>= 1) s += __shfl_xor_sync(0xffffffffu, s, o);
    float mu = s * (1.0f / 256.0f);
    float c[8], v2 = 0.f;
#pragma unroll
    for (int k = 0; k < 8; k++) { c[k] = r[k] - mu; v2 = fmaf(c[k], c[k], v2); }
#pragma unroll
    for (int o = 16; o; o >>= 1) v2 += __shfl_xor_sync(0xffffffffu, v2, o);
    float rstd = rsqrtf(v2 * (1.0f / 256.0f) + 1e-5f);

    const float4* gp = (const float4*)gamma;
    const float4* bp = (const float4*)beta;
    float4 g0 = gp[lane], g1 = gp[32 + lane];
    float4 p0 = bp[lane], p1 = bp[32 + lane];
    float4 o0, o1;
    o0.x = fmaf(c[0] * rstd, g0.x, p0.x);
    o0.y = fmaf(c[1] * rstd, g0.y, p0.y);
    o0.z = fmaf(c[2] * rstd, g0.z, p0.z);
    o0.w = fmaf(c[3] * rstd, g0.w, p0.w);
    o1.x = fmaf(c[4] * rstd, g1.x, p1.x);
    o1.y = fmaf(c[5] * rstd, g1.y, p1.y);
    o1.z = fmaf(c[6] * rstd, g1.z, p1.z);
    o1.w = fmaf(c[7] * rstd, g1.w, p1.w);
    float4* out = (float4*)(g_hn + i * 256);
    out[lane]      = o0;
    out[32 + lane] = o1;
}

// ---------------- launch ----------------
extern "C" void kernel_launch(void* const* d_in, const int* in_sizes, int n_in,
                              void* d_out, int out_size) {
    const float* x       = (const float*)d_in[0];
    const int*   ei      = (const int*)d_in[1];
    const float* W       = (const float*)d_in[3];
    const float* att_src = (const float*)d_in[4];
    const float* att_dst = (const float*)d_in[5];
    const float* bias    = (const float*)d_in[6];
    const float* ln_g    = (const float*)d_in[7];
    const float* ln_b    = (const float*)d_in[8];
    const float* W1      = (const float*)d_in[9];
    const float* b1      = (const float*)d_in[10];
    const float* W2      = (const float*)d_in[11];
    const float* b2      = (const float*)d_in[12];

    const int n = in_sizes[0] / DD;
    const int E = in_sizes[1] / 2;

    float *hn, *hid;
    int   *deg;
    cudaGetSymbolAddress((void**)&hn,  g_hn);
    cudaGetSymbolAddress((void**)&hid, g_hid);
    cudaGetSymbolAddress((void**)&deg, g_deg);

    static cudaStream_t s2 = nullptr;
    static cudaEvent_t ev_fork = nullptr, ev_join = nullptr;
    if (!s2) {
        cudaStreamCreateWithFlags(&s2, cudaStreamNonBlocking);
        cudaEventCreateWithFlags(&ev_fork, cudaEventDisableTiming);
        cudaEventCreateWithFlags(&ev_join, cudaEventDisableTiming);
    }

    dim3 gg((n + 127) / 128, 4);
    const int n4 = (n + 3) >> 2;
    const int nscan = (n4 + 1023) / 1024;

    cudaEventRecord(ev_fork, 0);
    cudaStreamWaitEvent(s2, ev_fork, 0);

    cudaMemsetAsync(deg, 0, n * sizeof(int), s2);
    deg_count<<<(E + 511) / 512, 512, 0, s2>>>(ei, E);
    scan_part<<<nscan, 1024, 0, s2>>>(n);
    scan_add <<<nscan, 1024, 0, s2>>>(n);
    csr_fill <<<(E + 255) / 256, 256, 0, s2>>>(ei, E);
    cudaEventRecord(ev_join, s2);

    // GEMM1: x@W -> bf16 g_xpb + fused attention logits
    gemm_tc<false, false, true><<<gg, 256>>>(x, W, nullptr, nullptr, att_src, att_dst, n);

    cudaStreamWaitEvent(0, ev_join, 0);

    gat_gather<<<(n * 32 + 255) / 256, 256>>>(x, bias, ln_g, ln_b, n);
    gemm_tc<true,  true, false><<<gg, 256>>>(hn,  W1, b1, hid, nullptr, nullptr, n);
    gemm_tc<false, true, false><<<gg, 256>>>(hid, W2, b2, (float*)d_out, nullptr, nullptr, n);
}

// round 11
// speedup vs baseline: 1.0942x; 1.0032x over previous
#include <cuda_runtime.h>
#include <cuda_bf16.h>

// ---------------- problem constants ----------------
#define DD 256
#define HH 8
#define N_MAX 50048
#define E_MAX 800000
#define NEG_SLOPE 0.2f

// ---------------- device scratch ----------------
__device__ __align__(256) unsigned g_xpb [N_MAX * 128];  // x@W as bf16x2 (128 words/row)
__device__ __align__(256) float    g_asrc[N_MAX * HH];
__device__ __align__(256) float    g_adst[N_MAX * HH];
__device__ __align__(256) float    g_hn  [N_MAX * DD];
__device__ __align__(256) float    g_hid [N_MAX * DD];
__device__ __align__(256) int      g_deg [N_MAX];
__device__ __align__(256) int      g_off [N_MAX];
__device__ __align__(256) int      g_cur [N_MAX];
__device__ __align__(256) int      g_srcl[E_MAX];
__device__ int g_bsum[64];

__device__ __forceinline__ float leaky(float v) {
    return v > 0.f ? v : NEG_SLOPE * v;
}

__device__ __forceinline__ float bfl(unsigned w) { return __uint_as_float(w << 16); }
__device__ __forceinline__ float bfh(unsigned w) { return __uint_as_float(w & 0xffff0000u); }

// ---------------- bf16-split helpers ----------------
__device__ __forceinline__ unsigned pack_hi(float x, float y) {
    unsigned r;
    asm("prmt.b32 %0, %1, %2, 0x7632;"
        : "=r"(r) : "r"(__float_as_uint(x)), "r"(__float_as_uint(y)));
    return r;
}
__device__ __forceinline__ unsigned pack_lo(float x, float y) {
    float hx = __uint_as_float(__float_as_uint(x) & 0xffff0000u);
    float hy = __uint_as_float(__float_as_uint(y) & 0xffff0000u);
    float lx = x - hx, ly = y - hy;
    unsigned r;
    asm("cvt.rn.bf16x2.f32 %0, %1, %2;" : "=r"(r) : "f"(ly), "f"(lx));
    return r;
}
__device__ __forceinline__ unsigned pack_rn(float x, float y) {
    unsigned r;
    asm("cvt.rn.bf16x2.f32 %0, %1, %2;" : "=r"(r) : "f"(y), "f"(x));
    return r;
}

__device__ __forceinline__ void mma16(float* c, const unsigned* a, const unsigned* b) {
    asm("mma.sync.aligned.m16n8k16.row.col.f32.bf16.bf16.f32 "
        "{%0,%1,%2,%3}, {%4,%5,%6,%7}, {%8,%9}, {%0,%1,%2,%3};"
        : "+f"(c[0]), "+f"(c[1]), "+f"(c[2]), "+f"(c[3])
        : "r"(a[0]), "r"(a[1]), "r"(a[2]), "r"(a[3]), "r"(b[0]), "r"(b[1]));
}

// ---------------- tensor-core GEMM (3xBF16 split, m16n8k16) ----------------
template <bool RELU, bool BIAS, bool ATTOUT>
__global__ __launch_bounds__(256)
void gemm_tc(const float* __restrict__ A, const float* __restrict__ B,
             const float* __restrict__ bias, float* __restrict__ C,
             const float* __restrict__ att_s, const float* __restrict__ att_d,
             int M) {
    __shared__ float As[128][36];
    __shared__ float Bs[32][68];
    const int tid  = threadIdx.x;
    const int lane = tid & 31;
    const int warp = tid >> 5;
    const int wm   = warp & 3;
    const int wn   = warp >> 2;
    const int brow = blockIdx.x * 128;
    const int bcol = blockIdx.y * 64;
    const int q    = lane >> 2;
    const int tq   = lane & 3;

    const int ar0 = tid >> 3;
    const int ac4 = (tid & 7) * 4;
    const int br  = tid >> 4;
    const int bc4 = (tid & 15) * 4;

    float acc[2][4][4];
#pragma unroll
    for (int mt = 0; mt < 2; mt++)
#pragma unroll
        for (int nt = 0; nt < 4; nt++)
#pragma unroll
            for (int k = 0; k < 4; k++) acc[mt][nt][k] = 0.f;

    float4 pa[4], pb[2];

#pragma unroll
    for (int j = 0; j < 4; j++) {
        int gr = brow + ar0 + 32 * j;
        pa[j] = (gr < M) ? *(const float4*)(A + gr * 256 + ac4)
                         : make_float4(0.f, 0.f, 0.f, 0.f);
    }
    pb[0] = *(const float4*)(B + br * 256 + bcol + bc4);
    pb[1] = *(const float4*)(B + (16 + br) * 256 + bcol + bc4);
#pragma unroll
    for (int j = 0; j < 4; j++) *(float4*)&As[ar0 + 32 * j][ac4] = pa[j];
    *(float4*)&Bs[br][bc4]      = pb[0];
    *(float4*)&Bs[16 + br][bc4] = pb[1];
    __syncthreads();

    for (int k0 = 0; k0 < 8; k0++) {
        if (k0 < 7) {
            int kb = (k0 + 1) * 32;
#pragma unroll
            for (int j = 0; j < 4; j++) {
                int gr = brow + ar0 + 32 * j;
                pa[j] = (gr < M) ? *(const float4*)(A + gr * 256 + kb + ac4)
                                 : make_float4(0.f, 0.f, 0.f, 0.f);
            }
            pb[0] = *(const float4*)(B + (kb + br) * 256 + bcol + bc4);
            pb[1] = *(const float4*)(B + (kb + 16 + br) * 256 + bcol + bc4);
        }

#pragma unroll
        for (int kk = 0; kk < 2; kk++) {
            const int kb = kk * 16;
            unsigned bh[4][2], bl[4][2];
#pragma unroll
            for (int nt = 0; nt < 4; nt++) {
                int col = wn * 32 + nt * 8 + q;
                int r0  = kb + 2 * tq;
                float x0 = Bs[r0][col],     x1 = Bs[r0 + 1][col];
                float x2 = Bs[r0 + 8][col], x3 = Bs[r0 + 9][col];
                bh[nt][0] = pack_hi(x0, x1); bl[nt][0] = pack_lo(x0, x1);
                bh[nt][1] = pack_hi(x2, x3); bl[nt][1] = pack_lo(x2, x3);
            }
            unsigned ah[2][4], al[2][4];
#pragma unroll
            for (int mt = 0; mt < 2; mt++) {
                int r0 = wm * 32 + mt * 16 + q;
                int c  = kb + 2 * tq;
                float2 p0 = *(float2*)&As[r0][c];
                float2 p1 = *(float2*)&As[r0 + 8][c];
                float2 p2 = *(float2*)&As[r0][c + 8];
                float2 p3 = *(float2*)&As[r0 + 8][c + 8];
                ah[mt][0] = pack_hi(p0.x, p0.y); al[mt][0] = pack_lo(p0.x, p0.y);
                ah[mt][1] = pack_hi(p1.x, p1.y); al[mt][1] = pack_lo(p1.x, p1.y);
                ah[mt][2] = pack_hi(p2.x, p2.y); al[mt][2] = pack_lo(p2.x, p2.y);
                ah[mt][3] = pack_hi(p3.x, p3.y); al[mt][3] = pack_lo(p3.x, p3.y);
            }
#pragma unroll
            for (int mt = 0; mt < 2; mt++)
#pragma unroll
                for (int nt = 0; nt < 4; nt++) {
                    mma16(acc[mt][nt], al[mt], bh[nt]);
                    mma16(acc[mt][nt], ah[mt], bl[nt]);
                    mma16(acc[mt][nt], ah[mt], bh[nt]);
                }
        }
        __syncthreads();
        if (k0 < 7) {
#pragma unroll
            for (int j = 0; j < 4; j++) *(float4*)&As[ar0 + 32 * j][ac4] = pa[j];
            *(float4*)&Bs[br][bc4]      = pb[0];
            *(float4*)&Bs[16 + br][bc4] = pb[1];
            __syncthreads();
        }
    }

    if (ATTOUT) {
        const int h = 2 * blockIdx.y + wn;
        float avs[4][2], avd[4][2];
#pragma unroll
        for (int nt = 0; nt < 4; nt++) {
            int ch = nt * 8 + 2 * tq;
            avs[nt][0] = att_s[h * 32 + ch];     avs[nt][1] = att_s[h * 32 + ch + 1];
            avd[nt][0] = att_d[h * 32 + ch];     avd[nt][1] = att_d[h * 32 + ch + 1];
        }
#pragma unroll
        for (int mt = 0; mt < 2; mt++) {
            int gr0 = brow + wm * 32 + mt * 16 + q;
            float ps0 = 0.f, pd0 = 0.f, ps1 = 0.f, pd1 = 0.f;
#pragma unroll
            for (int nt = 0; nt < 4; nt++) {
                int gc = bcol + wn * 32 + nt * 8 + 2 * tq;
                unsigned w0 = pack_rn(acc[mt][nt][0], acc[mt][nt][1]);
                unsigned w1 = pack_rn(acc[mt][nt][2], acc[mt][nt][3]);
                if (gr0 < M)     g_xpb[gr0 * 128 + (gc >> 1)]       = w0;
                if (gr0 + 8 < M) g_xpb[(gr0 + 8) * 128 + (gc >> 1)] = w1;
                ps0 = fmaf(acc[mt][nt][0], avs[nt][0], fmaf(acc[mt][nt][1], avs[nt][1], ps0));
                pd0 = fmaf(acc[mt][nt][0], avd[nt][0], fmaf(acc[mt][nt][1], avd[nt][1], pd0));
                ps1 = fmaf(acc[mt][nt][2], avs[nt][0], fmaf(acc[mt][nt][3], avs[nt][1], ps1));
                pd1 = fmaf(acc[mt][nt][2], avd[nt][0], fmaf(acc[mt][nt][3], avd[nt][1], pd1));
            }
            ps0 += __shfl_xor_sync(0xffffffffu, ps0, 1);
            ps0 += __shfl_xor_sync(0xffffffffu, ps0, 2);
            pd0 += __shfl_xor_sync(0xffffffffu, pd0, 1);
            pd0 += __shfl_xor_sync(0xffffffffu, pd0, 2);
            ps1 += __shfl_xor_sync(0xffffffffu, ps1, 1);
            ps1 += __shfl_xor_sync(0xffffffffu, ps1, 2);
            pd1 += __shfl_xor_sync(0xffffffffu, pd1, 1);
            pd1 += __shfl_xor_sync(0xffffffffu, pd1, 2);
            if (tq == 0) {
                if (gr0 < M)     { g_asrc[gr0 * 8 + h] = ps0;       g_adst[gr0 * 8 + h] = pd0; }
                if (gr0 + 8 < M) { g_asrc[(gr0 + 8) * 8 + h] = ps1; g_adst[(gr0 + 8) * 8 + h] = pd1; }
            }
        }
        return;
    }

#pragma unroll
    for (int mt = 0; mt < 2; mt++) {
        int gr0 = brow + wm * 32 + mt * 16 + q;
#pragma unroll
        for (int nt = 0; nt < 4; nt++) {
            int gc = bcol + wn * 32 + nt * 8 + 2 * tq;
            float bx = 0.f, by = 0.f;
            if (BIAS) { bx = bias[gc]; by = bias[gc + 1]; }
            float2 v0 = make_float2(acc[mt][nt][0] + bx, acc[mt][nt][1] + by);
            float2 v1 = make_float2(acc[mt][nt][2] + bx, acc[mt][nt][3] + by);
            if (RELU) {
                v0.x = fmaxf(v0.x, 0.f); v0.y = fmaxf(v0.y, 0.f);
                v1.x = fmaxf(v1.x, 0.f); v1.y = fmaxf(v1.y, 0.f);
            }
            if (gr0 < M)     *(float2*)(C + gr0 * 256 + gc)       = v0;
            if (gr0 + 8 < M) *(float2*)(C + (gr0 + 8) * 256 + gc) = v1;
        }
    }
}

// ---------------- CSR build ----------------
__global__ void deg_count(const int* __restrict__ ei, int E) {
    int e = blockIdx.x * blockDim.x + threadIdx.x;
    if (e >= E) return;
    atomicAdd(&g_deg[ei[E + e]], 1);
}

__global__ void scan_part(int n) {
    __shared__ int wsum[32];
    int tid = threadIdx.x, lane = tid & 31, wid = tid >> 5;
    int n4 = (n + 3) >> 2;
    int f = blockIdx.x * 1024 + tid;
    int4 v = make_int4(0, 0, 0, 0);
    if (f < n4) {
        if (f * 4 + 3 < n) v = ((const int4*)g_deg)[f];
        else {
            if (f * 4 + 0 < n) v.x = g_deg[f * 4 + 0];
            if (f * 4 + 1 < n) v.y = g_deg[f * 4 + 1];
            if (f * 4 + 2 < n) v.z = g_deg[f * 4 + 2];
        }
    }
    int tsum = v.x + v.y + v.z + v.w;
    int x = tsum;
#pragma unroll
    for (int o = 1; o < 32; o <<= 1) {
        int t = __shfl_up_sync(0xffffffffu, x, o);
        if (lane >= o) x += t;
    }
    if (lane == 31) wsum[wid] = x;
    __syncthreads();
    if (wid == 0) {
        int w = wsum[lane];
#pragma unroll
        for (int o = 1; o < 32; o <<= 1) {
            int t = __shfl_up_sync(0xffffffffu, w, o);
            if (lane >= o) w += t;
        }
        wsum[lane] = w;
    }
    __syncthreads();
    int excl = (wid ? wsum[wid - 1] : 0) + x - tsum;
    int4 o4;
    o4.x = excl;
    o4.y = o4.x + v.x;
    o4.z = o4.y + v.y;
    o4.w = o4.z + v.z;
    if (f < n4) {
        if (f * 4 + 3 < n) ((int4*)g_off)[f] = o4;
        else {
            if (f * 4 + 0 < n) g_off[f * 4 + 0] = o4.x;
            if (f * 4 + 1 < n) g_off[f * 4 + 1] = o4.y;
            if (f * 4 + 2 < n) g_off[f * 4 + 2] = o4.z;
        }
    }
    if (tid == 0) g_bsum[blockIdx.x] = wsum[31];
}

__global__ void scan_add(int n) {
    __shared__ int s_add;
    int tid = threadIdx.x;
    if (tid < 32) {
        int v = (tid < (int)blockIdx.x) ? g_bsum[tid] : 0;
#pragma unroll
        for (int o = 16; o; o >>= 1) v += __shfl_xor_sync(0xffffffffu, v, o);
        if (tid == 0) s_add = v;
    }
    __syncthreads();
    int add = s_add;
    int n4 = (n + 3) >> 2;
    int f = blockIdx.x * 1024 + tid;
    if (f >= n4) return;
    if (f * 4 + 3 < n) {
        int4 o = ((const int4*)g_off)[f];
        o.x += add; o.y += add; o.z += add; o.w += add;
        ((int4*)g_off)[f] = o;
        ((int4*)g_cur)[f] = o;
    } else {
#pragma unroll
        for (int j = 0; j < 3; j++)
            if (f * 4 + j < n) {
                int o = g_off[f * 4 + j] + add;
                g_off[f * 4 + j] = o;
                g_cur[f * 4 + j] = o;
            }
    }
}

__global__ void csr_fill(const int* __restrict__ ei, int E) {
    int e = blockIdx.x * blockDim.x + threadIdx.x;
    if (e >= E) return;
    int s = ei[e];
    int d = ei[E + e];
    int pos = atomicAdd(&g_cur[d], 1);
    g_srcl[pos] = s;
}

// ---------------- fused gather: lane owns 8 contiguous channels (one head) ----------------
__global__ void gat_gather(const float* __restrict__ x,
                           const float* __restrict__ bias,
                           const float* __restrict__ gamma,
                           const float* __restrict__ beta, int n) {
    int warp = (blockIdx.x * blockDim.x + threadIdx.x) >> 5;
    int lane = threadIdx.x & 31;
    if (warp >= n) return;
    const int i    = warp;
    const int hsel = lane >> 2;      // ex source lane for this lane's head

    float acc[8] = {0.f, 0.f, 0.f, 0.f, 0.f, 0.f, 0.f, 0.f};
    float den  = 0.f;
    float adst = (lane < 8) ? g_adst[i * 8 + lane] : 0.f;

    const int start = g_off[i];
    const int deg   = g_deg[i];
    const int* sl   = g_srcl + start;

#define EDGE_BODY(sk, exk)                                                   \
    {                                                                        \
        float a = __shfl_sync(0xffffffffu, exk, hsel);                       \
        uint4 v = *(const uint4*)(g_xpb + (sk) * 128 + lane * 4);            \
        acc[0] = fmaf(a, bfl(v.x), acc[0]); acc[1] = fmaf(a, bfh(v.x), acc[1]); \
        acc[2] = fmaf(a, bfl(v.y), acc[2]); acc[3] = fmaf(a, bfh(v.y), acc[3]); \
        acc[4] = fmaf(a, bfl(v.z), acc[4]); acc[5] = fmaf(a, bfh(v.z), acc[5]); \
        acc[6] = fmaf(a, bfl(v.w), acc[6]); acc[7] = fmaf(a, bfh(v.w), acc[7]); \
    }

    int e = 0;
    for (; e + 8 <= deg; e += 8) {
        int s0 = sl[e],     s1 = sl[e + 1], s2 = sl[e + 2], s3 = sl[e + 3];
        int s4 = sl[e + 4], s5 = sl[e + 5], s6 = sl[e + 6], s7 = sl[e + 7];
        float ex0 = 0.f, ex1 = 0.f, ex2 = 0.f, ex3 = 0.f;
        float ex4 = 0.f, ex5 = 0.f, ex6 = 0.f, ex7 = 0.f;
        if (lane < 8) {
            float l0 = g_asrc[s0 * 8 + lane];
            float l1 = g_asrc[s1 * 8 + lane];
            float l2 = g_asrc[s2 * 8 + lane];
            float l3 = g_asrc[s3 * 8 + lane];
            float l4 = g_asrc[s4 * 8 + lane];
            float l5 = g_asrc[s5 * 8 + lane];
            float l6 = g_asrc[s6 * 8 + lane];
            float l7 = g_asrc[s7 * 8 + lane];
            ex0 = __expf(leaky(l0 + adst)); ex1 = __expf(leaky(l1 + adst));
            ex2 = __expf(leaky(l2 + adst)); ex3 = __expf(leaky(l3 + adst));
            ex4 = __expf(leaky(l4 + adst)); ex5 = __expf(leaky(l5 + adst));
            ex6 = __expf(leaky(l6 + adst)); ex7 = __expf(leaky(l7 + adst));
            den += ((ex0 + ex1) + (ex2 + ex3)) + ((ex4 + ex5) + (ex6 + ex7));
        }
        EDGE_BODY(s0, ex0); EDGE_BODY(s1, ex1);
        EDGE_BODY(s2, ex2); EDGE_BODY(s3, ex3);
        EDGE_BODY(s4, ex4); EDGE_BODY(s5, ex5);
        EDGE_BODY(s6, ex6); EDGE_BODY(s7, ex7);
    }
    for (; e + 4 <= deg; e += 4) {
        int s0 = sl[e], s1 = sl[e + 1], s2 = sl[e + 2], s3 = sl[e + 3];
        float ex0 = 0.f, ex1 = 0.f, ex2 = 0.f, ex3 = 0.f;
        if (lane < 8) {
            float l0 = g_asrc[s0 * 8 + lane];
            float l1 = g_asrc[s1 * 8 + lane];
            float l2 = g_asrc[s2 * 8 + lane];
            float l3 = g_asrc[s3 * 8 + lane];
            ex0 = __expf(leaky(l0 + adst)); ex1 = __expf(leaky(l1 + adst));
            ex2 = __expf(leaky(l2 + adst)); ex3 = __expf(leaky(l3 + adst));
            den += (ex0 + ex1) + (ex2 + ex3);
        }
        EDGE_BODY(s0, ex0); EDGE_BODY(s1, ex1);
        EDGE_BODY(s2, ex2); EDGE_BODY(s3, ex3);
    }
    for (; e < deg; e++) {
        int s = sl[e];
        float ex = 0.f;
        if (lane < 8) {
            ex = __expf(leaky(g_asrc[s * 8 + lane] + adst));
            den += ex;
        }
        EDGE_BODY(s, ex);
    }

    // self loop
    {
        float ex = 0.f;
        if (lane < 8) {
            ex = __expf(leaky(g_asrc[i * 8 + lane] + adst));
            den += ex;
        }
        EDGE_BODY(i, ex);
    }
#undef EDGE_BODY

    float invd = 1.f / (den + 1e-16f);          // valid on lanes 0..7
    float inv  = __shfl_sync(0xffffffffu, invd, hsel);

    // bias + residual
    const float4* xr = (const float4*)(x + i * 256);
    const float4* bi = (const float4*)bias;
    float4 xv0 = xr[lane * 2], xv1 = xr[lane * 2 + 1];
    float4 b0  = bi[lane * 2], b1  = bi[lane * 2 + 1];
    float r[8];
    r[0] = fmaf(acc[0], inv, b0.x) + xv0.x;
    r[1] = fmaf(acc[1], inv, b0.y) + xv0.y;
    r[2] = fmaf(acc[2], inv, b0.z) + xv0.z;
    r[3] = fmaf(acc[3], inv, b0.w) + xv0.w;
    r[4] = fmaf(acc[4], inv, b1.x) + xv1.x;
    r[5] = fmaf(acc[5], inv, b1.y) + xv1.y;
    r[6] = fmaf(acc[6], inv, b1.z) + xv1.z;
    r[7] = fmaf(acc[7], inv, b1.w) + xv1.w;

    // warp LayerNorm
    float s = ((r[0] + r[1]) + (r[2] + r[3])) + ((r[4] + r[5]) + (r[6] + r[7]));
#pragma unroll
    for (int o = 16; o; o >>= 1) s += __shfl_xor_sync(0xffffffffu, s, o);
    float mu = s * (1.0f / 256.0f);
    float c[8], v2 = 0.f;
#pragma unroll
    for (int k = 0; k < 8; k++) { c[k] = r[k] - mu; v2 = fmaf(c[k], c[k], v2); }
#pragma unroll
    for (int o = 16; o; o >>= 1) v2 += __shfl_xor_sync(0xffffffffu, v2, o);
    float rstd = rsqrtf(v2 * (1.0f / 256.0f) + 1e-5f);

    const float4* gp = (const float4*)gamma;
    const float4* bp = (const float4*)beta;
    float4 g0 = gp[lane * 2], g1 = gp[lane * 2 + 1];
    float4 p0 = bp[lane * 2], p1 = bp[lane * 2 + 1];
    float4 o0, o1;
    o0.x = fmaf(c[0] * rstd, g0.x, p0.x);
    o0.y = fmaf(c[1] * rstd, g0.y, p0.y);
    o0.z = fmaf(c[2] * rstd, g0.z, p0.z);
    o0.w = fmaf(c[3] * rstd, g0.w, p0.w);
    o1.x = fmaf(c[4] * rstd, g1.x, p1.x);
    o1.y = fmaf(c[5] * rstd, g1.y, p1.y);
    o1.z = fmaf(c[6] * rstd, g1.z, p1.z);
    o1.w = fmaf(c[7] * rstd, g1.w, p1.w);
    float4* out = (float4*)(g_hn + i * 256);
    out[lane * 2]     = o0;
    out[lane * 2 + 1] = o1;
}

// ---------------- launch ----------------
extern "C" void kernel_launch(void* const* d_in, const int* in_sizes, int n_in,
                              void* d_out, int out_size) {
    const float* x       = (const float*)d_in[0];
    const int*   ei      = (const int*)d_in[1];
    const float* W       = (const float*)d_in[3];
    const float* att_src = (const float*)d_in[4];
    const float* att_dst = (const float*)d_in[5];
    const float* bias    = (const float*)d_in[6];
    const float* ln_g    = (const float*)d_in[7];
    const float* ln_b    = (const float*)d_in[8];
    const float* W1      = (const float*)d_in[9];
    const float* b1      = (const float*)d_in[10];
    const float* W2      = (const float*)d_in[11];
    const float* b2      = (const float*)d_in[12];

    const int n = in_sizes[0] / DD;
    const int E = in_sizes[1] / 2;

    float *hn, *hid;
    int   *deg;
    cudaGetSymbolAddress((void**)&hn,  g_hn);
    cudaGetSymbolAddress((void**)&hid, g_hid);
    cudaGetSymbolAddress((void**)&deg, g_deg);

    static cudaStream_t s2 = nullptr;
    static cudaEvent_t ev_fork = nullptr, ev_join = nullptr;
    if (!s2) {
        cudaStreamCreateWithFlags(&s2, cudaStreamNonBlocking);
        cudaEventCreateWithFlags(&ev_fork, cudaEventDisableTiming);
        cudaEventCreateWithFlags(&ev_join, cudaEventDisableTiming);
    }

    dim3 gg((n + 127) / 128, 4);
    const int n4 = (n + 3) >> 2;
    const int nscan = (n4 + 1023) / 1024;

    cudaEventRecord(ev_fork, 0);
    cudaStreamWaitEvent(s2, ev_fork, 0);

    cudaMemsetAsync(deg, 0, n * sizeof(int), s2);
    deg_count<<<(E + 511) / 512, 512, 0, s2>>>(ei, E);
    scan_part<<<nscan, 1024, 0, s2>>>(n);
    scan_add <<<nscan, 1024, 0, s2>>>(n);
    csr_fill <<<(E + 255) / 256, 256, 0, s2>>>(ei, E);
    cudaEventRecord(ev_join, s2);

    gemm_tc<false, false, true><<<gg, 256>>>(x, W, nullptr, nullptr, att_src, att_dst, n);

    cudaStreamWaitEvent(0, ev_join, 0);

    gat_gather<<<(n * 32 + 255) / 256, 256>>>(x, bias, ln_g, ln_b, n);
    gemm_tc<true,  true, false><<<gg, 256>>>(hn,  W1, b1, hid, nullptr, nullptr, n);
    gemm_tc<false, true, false><<<gg, 256>>>(hid, W2, b2, (float*)d_out, nullptr, nullptr, n);
}